// round 1
// baseline (speedup 1.0000x reference)
#include <cuda_runtime.h>
#include <math.h>

// Problem constants
#define Bb 4
#define Ll 4096
#define Hh 1024
#define Nn 16
#define Pc 128          // chunk length
#define NCk 32          // Ll / Pc
#define EPSV 1e-6f

// ---------------- scratch (static device globals; no allocation) ----------------
__device__ float  g_u  [(size_t)Bb*Hh*Ll];   // normalized, masked, (B,H,L)  64MB
__device__ float  g_yg [(size_t)Bb*Hh*Ll];   // gelu(ssm output), (B,H,L)    64MB
__device__ float  g_rstd[Bb*Ll];
__device__ float2 g_lam [Hh*Nn];             // exp(dtA)
__device__ float2 g_lamP[Hh*Nn];             // exp(dtA)^P
__device__ float2 g_cd2 [Hh*Nn];             // 2 * C * (exp(dtA)-1)/A
__device__ float2 g_Sloc[(size_t)Bb*Hh*NCk*Nn];  // 16MB
__device__ float2 g_Sin [(size_t)Bb*Hh*NCk*Nn];  // 16MB

// ---------------- kernel 0: per-(h,n) constants in double ----------------
__global__ void precompute_kernel(const float* __restrict__ log_dt,
                                  const float* __restrict__ log_A_real,
                                  const float* __restrict__ A_imag,
                                  const float* __restrict__ C_real,
                                  const float* __restrict__ C_imag) {
    int idx = blockIdx.x * blockDim.x + threadIdx.x;
    if (idx >= Hh * Nn) return;
    int h = idx / Nn;
    double dt  = exp((double)log_dt[h]);
    double Are = -exp((double)log_A_real[idx]);
    double Aim = (double)A_imag[idx];
    double dre = Are * dt, dim = Aim * dt;
    double er  = exp(dre);
    double lr  = er * cos(dim), li = er * sin(dim);
    g_lam[idx] = make_float2((float)lr, (float)li);
    double erp = exp(dre * (double)Pc);
    g_lamP[idx] = make_float2((float)(erp * cos(dim * (double)Pc)),
                              (float)(erp * sin(dim * (double)Pc)));
    // Cd = C*(lam-1)/A ; store 2*Cd
    double e1r = lr - 1.0, e1i = li;
    double Cr = (double)C_real[idx], Ci = (double)C_imag[idx];
    double nr = Cr * e1r - Ci * e1i;
    double ni = Cr * e1i + Ci * e1r;
    double den = Are * Are + Aim * Aim;
    double cdr = (nr * Are + ni * Aim) / den;
    double cdi = (ni * Are - nr * Aim) / den;
    g_cd2[idx] = make_float2((float)(2.0 * cdr), (float)(2.0 * cdi));
}

// ---------------- kernel 1: RMSNorm rstd, warp per (b,l) row ----------------
__global__ void rstd_kernel(const float* __restrict__ hs) {
    int gt   = blockIdx.x * blockDim.x + threadIdx.x;
    int row  = gt >> 5;
    int lane = gt & 31;
    if (row >= Bb * Ll) return;
    const float4* rp = (const float4*)(hs + (size_t)row * Hh);
    float s = 0.f;
#pragma unroll
    for (int i = 0; i < 8; i++) {
        float4 v = rp[i * 32 + lane];
        s += v.x * v.x + v.y * v.y + v.z * v.z + v.w * v.w;
    }
#pragma unroll
    for (int o = 16; o; o >>= 1) s += __shfl_xor_sync(0xffffffffu, s, o);
    if (lane == 0) g_rstd[row] = rsqrtf(s * (1.0f / Hh) + EPSV);
}

// ---------------- kernel 2: normalize + mask + transpose to (B,H,L) ----------------
__global__ void norm_transpose_kernel(const float* __restrict__ hs,
                                      const float* __restrict__ mask,
                                      const float* __restrict__ w) {
    __shared__ float tile[32][33];
    int b  = blockIdx.z;
    int l0 = blockIdx.y * 32;
    int h0 = blockIdx.x * 32;
    int tx = threadIdx.x, ty = threadIdx.y;  // (32,8)
    float wv = w[h0 + tx];
#pragma unroll
    for (int r = 0; r < 4; r++) {
        int l = l0 + ty + r * 8;
        float sc = g_rstd[b * Ll + l] * mask[b * Ll + l];
        tile[ty + r * 8][tx] = hs[((size_t)(b * Ll + l)) * Hh + h0 + tx] * sc * wv;
    }
    __syncthreads();
#pragma unroll
    for (int r = 0; r < 4; r++) {
        int h = h0 + ty + r * 8;
        g_u[((size_t)(b * Hh + h)) * Ll + l0 + tx] = tile[tx][ty + r * 8];
    }
}

// ---------------- kernel 3: per-chunk local end-states (warp per (b,h), lane=chunk) -------
__global__ void scan_local_kernel() {
    int gt = blockIdx.x * blockDim.x + threadIdx.x;
    int bh = gt >> 5;
    int c  = gt & 31;
    int hh = bh & (Hh - 1);
    float lr[Nn], li[Nn], sr[Nn], si[Nn];
#pragma unroll
    for (int n = 0; n < Nn; n++) {
        float2 v = g_lam[hh * Nn + n];
        lr[n] = v.x; li[n] = v.y; sr[n] = 0.f; si[n] = 0.f;
    }
    const float4* up = (const float4*)(g_u + (size_t)bh * Ll + c * Pc);
#pragma unroll 2
    for (int q = 0; q < Pc / 4; q++) {
        float4 uv = up[q];
        float xs[4] = {uv.x, uv.y, uv.z, uv.w};
#pragma unroll
        for (int e = 0; e < 4; e++) {
            float x = xs[e];
#pragma unroll
            for (int n = 0; n < Nn; n++) {
                float nr = fmaf(lr[n], sr[n], fmaf(-li[n], si[n], x));
                float ni = fmaf(lr[n], si[n], li[n] * sr[n]);
                sr[n] = nr; si[n] = ni;
            }
        }
    }
    float2* outp = g_Sloc + ((size_t)bh * NCk + c) * Nn;
#pragma unroll
    for (int n = 0; n < Nn; n++) outp[n] = make_float2(sr[n], si[n]);
}

// ---------------- kernel 4: inter-chunk combine (thread per (b,h,n)) ----------------
__global__ void scan_combine_kernel() {
    int t = blockIdx.x * blockDim.x + threadIdx.x;
    if (t >= Bb * Hh * Nn) return;
    int n  = t & (Nn - 1);
    int bh = t >> 4;
    int hh = bh & (Hh - 1);
    float2 lp = g_lamP[hh * Nn + n];
    float sre = 0.f, sim = 0.f;
#pragma unroll
    for (int c = 0; c < NCk; c++) {
        size_t idx = ((size_t)bh * NCk + c) * Nn + n;
        g_Sin[idx] = make_float2(sre, sim);
        float2 sl = g_Sloc[idx];
        float nr = fmaf(lp.x, sre, fmaf(-lp.y, sim, sl.x));
        float ni = fmaf(lp.x, sim, fmaf(lp.y, sre, sl.y));
        sre = nr; sim = ni;
    }
}

// ---------------- kernel 5: output scan + D skip + exact GELU ----------------
__global__ void scan_out_kernel(const float* __restrict__ Dvec) {
    int gt = blockIdx.x * blockDim.x + threadIdx.x;
    int bh = gt >> 5;
    int c  = gt & 31;
    int hh = bh & (Hh - 1);
    float lr[Nn], li[Nn], cr[Nn], ci[Nn], sr[Nn], si[Nn];
#pragma unroll
    for (int n = 0; n < Nn; n++) {
        float2 v = g_lam[hh * Nn + n];  lr[n] = v.x; li[n] = v.y;
        float2 cc = g_cd2[hh * Nn + n]; cr[n] = cc.x; ci[n] = cc.y;
        float2 s0 = g_Sin[((size_t)bh * NCk + c) * Nn + n];
        sr[n] = s0.x; si[n] = s0.y;
    }
    float Dh = Dvec[hh];
    const float4* up = (const float4*)(g_u  + (size_t)bh * Ll + c * Pc);
    float4*       yp = (float4*)      (g_yg + (size_t)bh * Ll + c * Pc);
#pragma unroll 2
    for (int q = 0; q < Pc / 4; q++) {
        float4 uv = up[q];
        float xs[4] = {uv.x, uv.y, uv.z, uv.w};
        float ys[4];
#pragma unroll
        for (int e = 0; e < 4; e++) {
            float x = xs[e];
            float y = Dh * x;
#pragma unroll
            for (int n = 0; n < Nn; n++) {
                float nr = fmaf(lr[n], sr[n], fmaf(-li[n], si[n], x));
                float ni = fmaf(lr[n], si[n], li[n] * sr[n]);
                sr[n] = nr; si[n] = ni;
                y = fmaf(cr[n], nr, y);
                y = fmaf(-ci[n], ni, y);
            }
            // exact GELU
            ys[e] = 0.5f * y * (1.0f + erff(y * 0.70710678118654752f));
        }
        yp[q] = make_float4(ys[0], ys[1], ys[2], ys[3]);
    }
}

// ---------------- kernel 6: fused GEMM (both GLU halves) + sigmoid-gate + residual -------
// z[o, n] = sum_k w[o,k] * yg[k, n],  o in [0,2048), n = b*L + l  (K=1024, N=16384)
// out[n, h] = hs[n, h] + (z[h,n]+bias[h]) * sigmoid(z[h+1024,n]+bias[h+1024])
#define GBM 64
#define GBN 128
#define GBK 8
__global__ __launch_bounds__(256) void gemm_glu_kernel(const float* __restrict__ wmat,
                                                       const float* __restrict__ bias,
                                                       const float* __restrict__ hs,
                                                       float* __restrict__ out) {
    __shared__ float As[GBK][GBM];
    __shared__ float Gs[GBK][GBM];
    __shared__ float Bs[GBK][GBN];
    int o0 = blockIdx.x * GBM;   // 0..960
    int n0 = blockIdx.y * GBN;   // 0..16256
    int tid = threadIdx.x;

    float acc_a[4][8], acc_g[4][8];
#pragma unroll
    for (int i = 0; i < 4; i++)
#pragma unroll
        for (int j = 0; j < 8; j++) { acc_a[i][j] = 0.f; acc_g[i][j] = 0.f; }

    // global->shared load mapping
    int ar = tid >> 2;              // 0..63  (o row)
    int ak = (tid & 3) * 2;         // 0,2,4,6 (k col, float2)
    int bk = tid >> 5;              // 0..7   (k row)
    int bn = (tid & 31) * 4;        // 0..124 (n col, float4)
    const float* Aptr = wmat + (size_t)(o0 + ar) * 1024 + ak;
    const float* Gptr = wmat + (size_t)(1024 + o0 + ar) * 1024 + ak;
    int gn = n0 + bn;
    int batch = gn >> 12;           // /4096
    int lpos  = gn & 4095;
    const float* Bptr = g_yg + ((size_t)batch * Hh + bk) * Ll + lpos;

    int ty = tid >> 4;              // 0..15 -> o = ty*4
    int tx = tid & 15;              // 0..15 -> n cols {tx*4..+3} and {64+tx*4..+3}

    for (int k0 = 0; k0 < 1024; k0 += GBK) {
        float2 av = *(const float2*)(Aptr + k0);
        float2 gv = *(const float2*)(Gptr + k0);
        float4 bv = *(const float4*)(Bptr + (size_t)k0 * Ll);
        As[ak][ar] = av.x; As[ak + 1][ar] = av.y;
        Gs[ak][ar] = gv.x; Gs[ak + 1][ar] = gv.y;
        *(float4*)&Bs[bk][bn] = bv;
        __syncthreads();
#pragma unroll
        for (int kk = 0; kk < GBK; kk++) {
            float af[4], gf[4], bf[8];
            *(float4*)af = *(const float4*)&As[kk][ty * 4];
            *(float4*)gf = *(const float4*)&Gs[kk][ty * 4];
            *(float4*)(bf)     = *(const float4*)&Bs[kk][tx * 4];
            *(float4*)(bf + 4) = *(const float4*)&Bs[kk][64 + tx * 4];
#pragma unroll
            for (int i = 0; i < 4; i++)
#pragma unroll
                for (int j = 0; j < 8; j++) {
                    acc_a[i][j] = fmaf(af[i], bf[j], acc_a[i][j]);
                    acc_g[i][j] = fmaf(gf[i], bf[j], acc_g[i][j]);
                }
        }
        __syncthreads();
    }

    float ba[4], bg[4];
#pragma unroll
    for (int i = 0; i < 4; i++) {
        ba[i] = bias[o0 + ty * 4 + i];
        bg[i] = bias[1024 + o0 + ty * 4 + i];
    }
#pragma unroll
    for (int j = 0; j < 8; j++) {
        int ncol = (j < 4) ? (tx * 4 + j) : (64 + tx * 4 + (j - 4));
        size_t obase = (size_t)(n0 + ncol) * 1024 + o0 + ty * 4;
        float4 hv = *(const float4*)(hs + obase);
        float4 ov;
        {
            float a0 = acc_a[0][j] + ba[0], g0 = acc_g[0][j] + bg[0];
            float a1 = acc_a[1][j] + ba[1], g1 = acc_g[1][j] + bg[1];
            float a2 = acc_a[2][j] + ba[2], g2 = acc_g[2][j] + bg[2];
            float a3 = acc_a[3][j] + ba[3], g3 = acc_g[3][j] + bg[3];
            ov.x = hv.x + a0 * (1.0f / (1.0f + expf(-g0)));
            ov.y = hv.y + a1 * (1.0f / (1.0f + expf(-g1)));
            ov.z = hv.z + a2 * (1.0f / (1.0f + expf(-g2)));
            ov.w = hv.w + a3 * (1.0f / (1.0f + expf(-g3)));
        }
        *(float4*)(out + obase) = ov;
    }
}

// ---------------- launch ----------------
extern "C" void kernel_launch(void* const* d_in, const int* in_sizes, int n_in,
                              void* d_out, int out_size) {
    const float* hidden     = (const float*)d_in[0];   // (B,L,H)
    const float* attn_mask  = (const float*)d_in[1];   // (B,L)
    const float* norm_w     = (const float*)d_in[2];   // (H)
    const float* log_dt     = (const float*)d_in[3];   // (H)
    const float* log_A_real = (const float*)d_in[4];   // (H,N)
    const float* A_imag     = (const float*)d_in[5];   // (H,N)
    const float* C_real     = (const float*)d_in[6];   // (H,N)
    const float* C_imag     = (const float*)d_in[7];   // (H,N)
    const float* Dvec       = (const float*)d_in[8];   // (H)
    const float* out_w      = (const float*)d_in[9];   // (2H,H)
    const float* out_b      = (const float*)d_in[10];  // (2H)
    float* out = (float*)d_out;                        // (B,L,H)

    precompute_kernel<<<(Hh * Nn + 127) / 128, 128>>>(log_dt, log_A_real, A_imag, C_real, C_imag);
    rstd_kernel<<<(Bb * Ll * 32) / 256, 256>>>(hidden);
    norm_transpose_kernel<<<dim3(Hh / 32, Ll / 32, Bb), dim3(32, 8)>>>(hidden, attn_mask, norm_w);
    scan_local_kernel<<<(Bb * Hh * 32) / 256, 256>>>();
    scan_combine_kernel<<<(Bb * Hh * Nn) / 256, 256>>>();
    scan_out_kernel<<<(Bb * Hh * 32) / 256, 256>>>(Dvec);
    gemm_glu_kernel<<<dim3(Hh / GBM, (Bb * Ll) / GBN), 256>>>(out_w, out_b, hidden, out);
}

// round 3
// speedup vs baseline: 1.8764x; 1.8764x over previous
#include <cuda_runtime.h>
#include <cuda_bf16.h>
#include <math.h>
#include <stdint.h>

// Problem constants
#define Bb 4
#define Ll 4096
#define Hh 1024
#define Nn 16
#define Pc 128          // chunk length
#define NCk 32          // Ll / Pc
#define EPSV 1e-6f

// ---------------- scratch (static device globals; no allocation) ----------------
__device__ float  g_u  [(size_t)Bb*Hh*Ll];   // normalized, masked, (B,H,L)  64MB
__device__ float  g_yg [(size_t)Bb*Hh*Ll];   // gelu(ssm output), (B,H,L)    64MB
__device__ float  g_rstd[Bb*Ll];
__device__ float2 g_lam [Hh*Nn];
__device__ float2 g_lamP[Hh*Nn];
__device__ float2 g_cd2 [Hh*Nn];
__device__ float2 g_Sloc[(size_t)Bb*Hh*NCk*Nn];
__device__ float2 g_Sin [(size_t)Bb*Hh*NCk*Nn];
// bf16 split operands (packed pairs along k: low 16 bits = even k)
__device__ unsigned int g_wh2 [2048u*512u];          // weight hi [o][k/2]  4MB
__device__ unsigned int g_wl2 [2048u*512u];          // weight lo           4MB
__device__ unsigned int g_ygh2[(size_t)16384u*512u]; // ygT hi [n][k/2]    32MB
__device__ unsigned int g_ygl2[(size_t)16384u*512u]; // ygT lo             32MB
__device__ float g_zt[(size_t)16384u*2048u];         // z^T [n][o]        128MB

// ================= PTX helpers (all legal on base compute_103) =================
__device__ __forceinline__ uint32_t smem_u32(const void* p) {
    uint32_t a;
    asm("{ .reg .u64 t; cvta.to.shared.u64 t, %1; cvt.u32.u64 %0, t; }" : "=r"(a) : "l"(p));
    return a;
}
__device__ __forceinline__ void cp16(uint32_t dst, const void* src) {
    asm volatile("cp.async.cg.shared.global [%0], [%1], 16;" :: "r"(dst), "l"(src));
}
__device__ __forceinline__ void cp_commit() { asm volatile("cp.async.commit_group;"); }
__device__ __forceinline__ void cp_wait2()  { asm volatile("cp.async.wait_group 2;"); }
__device__ __forceinline__ void ldsm4(uint32_t* r, uint32_t addr) {
    asm volatile("ldmatrix.sync.aligned.m8n8.x4.shared.b16 {%0,%1,%2,%3}, [%4];"
                 : "=r"(r[0]), "=r"(r[1]), "=r"(r[2]), "=r"(r[3]) : "r"(addr));
}
__device__ __forceinline__ void mma16816(float* d, const uint32_t* a, const uint32_t* b) {
    asm volatile("mma.sync.aligned.m16n8k16.row.col.f32.bf16.bf16.f32 "
                 "{%0,%1,%2,%3}, {%4,%5,%6,%7}, {%8,%9}, {%0,%1,%2,%3};"
                 : "+f"(d[0]), "+f"(d[1]), "+f"(d[2]), "+f"(d[3])
                 : "r"(a[0]), "r"(a[1]), "r"(a[2]), "r"(a[3]), "r"(b[0]), "r"(b[1]));
}

// ---------------- kernel 0: per-(h,n) constants in double ----------------
__global__ void precompute_kernel(const float* __restrict__ log_dt,
                                  const float* __restrict__ log_A_real,
                                  const float* __restrict__ A_imag,
                                  const float* __restrict__ C_real,
                                  const float* __restrict__ C_imag) {
    int idx = blockIdx.x * blockDim.x + threadIdx.x;
    if (idx >= Hh * Nn) return;
    int h = idx / Nn;
    double dt  = exp((double)log_dt[h]);
    double Are = -exp((double)log_A_real[idx]);
    double Aim = (double)A_imag[idx];
    double dre = Are * dt, dim = Aim * dt;
    double er  = exp(dre);
    double lr  = er * cos(dim), li = er * sin(dim);
    g_lam[idx] = make_float2((float)lr, (float)li);
    double erp = exp(dre * (double)Pc);
    g_lamP[idx] = make_float2((float)(erp * cos(dim * (double)Pc)),
                              (float)(erp * sin(dim * (double)Pc)));
    double e1r = lr - 1.0, e1i = li;
    double Cr = (double)C_real[idx], Ci = (double)C_imag[idx];
    double nr = Cr * e1r - Ci * e1i;
    double ni = Cr * e1i + Ci * e1r;
    double den = Are * Are + Aim * Aim;
    double cdr = (nr * Are + ni * Aim) / den;
    double cdi = (ni * Are - nr * Aim) / den;
    g_cd2[idx] = make_float2((float)(2.0 * cdr), (float)(2.0 * cdi));
}

// ---------------- kernel 1: RMSNorm rstd ----------------
__global__ void rstd_kernel(const float* __restrict__ hs) {
    int gt   = blockIdx.x * blockDim.x + threadIdx.x;
    int row  = gt >> 5;
    int lane = gt & 31;
    if (row >= Bb * Ll) return;
    const float4* rp = (const float4*)(hs + (size_t)row * Hh);
    float s = 0.f;
#pragma unroll
    for (int i = 0; i < 8; i++) {
        float4 v = rp[i * 32 + lane];
        s += v.x * v.x + v.y * v.y + v.z * v.z + v.w * v.w;
    }
#pragma unroll
    for (int o = 16; o; o >>= 1) s += __shfl_xor_sync(0xffffffffu, s, o);
    if (lane == 0) g_rstd[row] = rsqrtf(s * (1.0f / Hh) + EPSV);
}

// ---------------- kernel 2: normalize + mask + transpose to (B,H,L) ----------------
__global__ void norm_transpose_kernel(const float* __restrict__ hs,
                                      const float* __restrict__ mask,
                                      const float* __restrict__ w) {
    __shared__ float tile[32][33];
    int b  = blockIdx.z;
    int l0 = blockIdx.y * 32;
    int h0 = blockIdx.x * 32;
    int tx = threadIdx.x, ty = threadIdx.y;
    float wv = w[h0 + tx];
#pragma unroll
    for (int r = 0; r < 4; r++) {
        int l = l0 + ty + r * 8;
        float sc = g_rstd[b * Ll + l] * mask[b * Ll + l];
        tile[ty + r * 8][tx] = hs[((size_t)(b * Ll + l)) * Hh + h0 + tx] * sc * wv;
    }
    __syncthreads();
#pragma unroll
    for (int r = 0; r < 4; r++) {
        int h = h0 + ty + r * 8;
        g_u[((size_t)(b * Hh + h)) * Ll + l0 + tx] = tile[tx][ty + r * 8];
    }
}

// ---------------- kernel 3: per-chunk local end-states ----------------
__global__ void scan_local_kernel() {
    int gt = blockIdx.x * blockDim.x + threadIdx.x;
    int bh = gt >> 5;
    int c  = gt & 31;
    int hh = bh & (Hh - 1);
    float lr[Nn], li[Nn], sr[Nn], si[Nn];
#pragma unroll
    for (int n = 0; n < Nn; n++) {
        float2 v = g_lam[hh * Nn + n];
        lr[n] = v.x; li[n] = v.y; sr[n] = 0.f; si[n] = 0.f;
    }
    const float4* up = (const float4*)(g_u + (size_t)bh * Ll + c * Pc);
#pragma unroll 2
    for (int q = 0; q < Pc / 4; q++) {
        float4 uv = up[q];
        float xs[4] = {uv.x, uv.y, uv.z, uv.w};
#pragma unroll
        for (int e = 0; e < 4; e++) {
            float x = xs[e];
#pragma unroll
            for (int n = 0; n < Nn; n++) {
                float nr = fmaf(lr[n], sr[n], fmaf(-li[n], si[n], x));
                float ni = fmaf(lr[n], si[n], li[n] * sr[n]);
                sr[n] = nr; si[n] = ni;
            }
        }
    }
    float2* outp = g_Sloc + ((size_t)bh * NCk + c) * Nn;
#pragma unroll
    for (int n = 0; n < Nn; n++) outp[n] = make_float2(sr[n], si[n]);
}

// ---------------- kernel 4: inter-chunk combine ----------------
__global__ void scan_combine_kernel() {
    int t = blockIdx.x * blockDim.x + threadIdx.x;
    if (t >= Bb * Hh * Nn) return;
    int n  = t & (Nn - 1);
    int bh = t >> 4;
    int hh = bh & (Hh - 1);
    float2 lp = g_lamP[hh * Nn + n];
    float sre = 0.f, sim = 0.f;
#pragma unroll
    for (int c = 0; c < NCk; c++) {
        size_t idx = ((size_t)bh * NCk + c) * Nn + n;
        g_Sin[idx] = make_float2(sre, sim);
        float2 sl = g_Sloc[idx];
        float nr = fmaf(lp.x, sre, fmaf(-lp.y, sim, sl.x));
        float ni = fmaf(lp.x, sim, fmaf(lp.y, sre, sl.y));
        sre = nr; sim = ni;
    }
}

// ---------------- kernel 5: output scan + D skip + exact GELU ----------------
__global__ void scan_out_kernel(const float* __restrict__ Dvec) {
    int gt = blockIdx.x * blockDim.x + threadIdx.x;
    int bh = gt >> 5;
    int c  = gt & 31;
    int hh = bh & (Hh - 1);
    float lr[Nn], li[Nn], cr[Nn], ci[Nn], sr[Nn], si[Nn];
#pragma unroll
    for (int n = 0; n < Nn; n++) {
        float2 v = g_lam[hh * Nn + n];  lr[n] = v.x; li[n] = v.y;
        float2 cc = g_cd2[hh * Nn + n]; cr[n] = cc.x; ci[n] = cc.y;
        float2 s0 = g_Sin[((size_t)bh * NCk + c) * Nn + n];
        sr[n] = s0.x; si[n] = s0.y;
    }
    float Dh = Dvec[hh];
    const float4* up = (const float4*)(g_u  + (size_t)bh * Ll + c * Pc);
    float4*       yp = (float4*)      (g_yg + (size_t)bh * Ll + c * Pc);
#pragma unroll 2
    for (int q = 0; q < Pc / 4; q++) {
        float4 uv = up[q];
        float xs[4] = {uv.x, uv.y, uv.z, uv.w};
        float ys[4];
#pragma unroll
        for (int e = 0; e < 4; e++) {
            float x = xs[e];
            float y = Dh * x;
#pragma unroll
            for (int n = 0; n < Nn; n++) {
                float nr = fmaf(lr[n], sr[n], fmaf(-li[n], si[n], x));
                float ni = fmaf(lr[n], si[n], li[n] * sr[n]);
                sr[n] = nr; si[n] = ni;
                y = fmaf(cr[n], nr, y);
                y = fmaf(-ci[n], ni, y);
            }
            ys[e] = 0.5f * y * (1.0f + erff(y * 0.70710678118654752f));
        }
        yp[q] = make_float4(ys[0], ys[1], ys[2], ys[3]);
    }
}

// ---------------- kernel 5b: weight fp32 -> bf16 hi/lo split ----------------
__global__ void convert_w_kernel(const float* __restrict__ wmat) {
    unsigned int i = blockIdx.x * blockDim.x + threadIdx.x;
    if (i >= 2048u * 512u) return;
    float2 v = ((const float2*)wmat)[i];
    __nv_bfloat16 h0 = __float2bfloat16_rn(v.x);
    __nv_bfloat16 h1 = __float2bfloat16_rn(v.y);
    __nv_bfloat16 l0 = __float2bfloat16_rn(v.x - __bfloat162float(h0));
    __nv_bfloat16 l1 = __float2bfloat16_rn(v.y - __bfloat162float(h1));
    g_wh2[i] = (unsigned int)__bfloat16_as_ushort(h0) |
               ((unsigned int)__bfloat16_as_ushort(h1) << 16);
    g_wl2[i] = (unsigned int)__bfloat16_as_ushort(l0) |
               ((unsigned int)__bfloat16_as_ushort(l1) << 16);
}

// ---------------- kernel 5c: transpose yg (b,h,l)->[n][k] + bf16 hi/lo split -------
__global__ void transpose_yg_kernel() {
    __shared__ float tile[64][33];
    int b  = blockIdx.z;
    int l0 = blockIdx.y * 32;
    int h0 = blockIdx.x * 64;
    int tx = threadIdx.x, ty = threadIdx.y;  // (32, 8)
#pragma unroll
    for (int r = 0; r < 8; r++) {
        int h = h0 + ty + r * 8;
        tile[ty + r * 8][tx] = g_yg[((size_t)(b * Hh + h)) * Ll + l0 + tx];
    }
    __syncthreads();
#pragma unroll
    for (int r = 0; r < 4; r++) {
        int lrow = ty + r * 8;
        size_t n = (size_t)b * Ll + l0 + lrow;
        float v0 = tile[2 * tx][lrow];
        float v1 = tile[2 * tx + 1][lrow];
        __nv_bfloat16 h0b = __float2bfloat16_rn(v0);
        __nv_bfloat16 h1b = __float2bfloat16_rn(v1);
        __nv_bfloat16 l0b = __float2bfloat16_rn(v0 - __bfloat162float(h0b));
        __nv_bfloat16 l1b = __float2bfloat16_rn(v1 - __bfloat162float(h1b));
        g_ygh2[n * 512 + (h0 >> 1) + tx] =
            (unsigned int)__bfloat16_as_ushort(h0b) | ((unsigned int)__bfloat16_as_ushort(h1b) << 16);
        g_ygl2[n * 512 + (h0 >> 1) + tx] =
            (unsigned int)__bfloat16_as_ushort(l0b) | ((unsigned int)__bfloat16_as_ushort(l1b) << 16);
    }
}

// ---------------- kernel 6: mma.sync bf16x3 GEMM -> z^T ----------------
// z[o,n] = sum_k W[o,k]*Y[k,n] via AhBh + AhBl + AlBh, fp32 accumulators.
// CTA tile 128(o) x 128(n), K-chunk 32, 3-stage cp.async pipeline.
// smem stage: 4 regions (Ah, Al, Bh, Bl), each 128 rows x 80B (64B data + 16B pad).
#define ROWB   80
#define REGION 10240            // 128*80
#define STAGEB 40960            // 4 regions
#define GEMM_SMEM (3 * STAGEB)  // 122880

__device__ __forceinline__ void load_stage(uint32_t sbase, int s, int chunk, int by, int bx) {
    int tid = threadIdx.x;
    uint32_t stb = sbase + s * STAGEB;
    int kp0 = chunk * 16;  // uint32 pair offset within row
#pragma unroll
    for (int i = 0; i < 8; i++) {
        int t   = (i & 1) * 256 + tid;     // 0..511
        int row = t >> 2, ch = t & 3;
        uint32_t dst = stb + (unsigned)(i >> 1) * REGION + row * ROWB + ch * 16;
        const unsigned int* src;
        if ((i >> 1) == 0)      src = g_wh2  + (size_t)(by * 128 + row) * 512;
        else if ((i >> 1) == 1) src = g_wl2  + (size_t)(by * 128 + row) * 512;
        else if ((i >> 1) == 2) src = g_ygh2 + (size_t)(bx * 128 + row) * 512;
        else                    src = g_ygl2 + (size_t)(bx * 128 + row) * 512;
        cp16(dst, src + kp0 + ch * 4);
    }
}

__global__ __launch_bounds__(256) void gemm_mma_kernel() {
    extern __shared__ char smem[];
    uint32_t sbase = smem_u32(smem);
    int tid  = threadIdx.x;
    int wid  = tid >> 5;
    int lane = tid & 31;
    int by = blockIdx.x;   // o-tile: o0 = by*128   (fast index -> CTAs sharing B co-resident)
    int bx = blockIdx.y;   // n-tile: n0 = bx*128

    int wm = (wid & 1) * 64;        // warp m origin (2 warps along m)
    int wn = (wid >> 1) * 32;       // warp n origin (4 warps along n)
    int g = lane >> 3, r = lane & 7;
    uint32_t aOff = (uint32_t)(wm + (g & 1) * 8 + r) * ROWB + (uint32_t)(g >> 1) * 16;
    uint32_t bOff = (uint32_t)(wn + (g >> 1) * 8 + r) * ROWB + (uint32_t)(g & 1) * 16;

    float acc[64];
#pragma unroll
    for (int i = 0; i < 64; i++) acc[i] = 0.f;

    // prologue: 3 stages in flight
#pragma unroll
    for (int p = 0; p < 3; p++) { load_stage(sbase, p, p, by, bx); cp_commit(); }

    for (int c = 0; c < 32; c++) {
        int s = c % 3;
        cp_wait2();
        __syncthreads();
        uint32_t ab = sbase + s * STAGEB;
#pragma unroll
        for (int ks = 0; ks < 2; ks++) {
            uint32_t koff = ks * 32;
            uint32_t bfh[8], bfl[8], af[16];
            ldsm4(&bfh[0], ab + 2 * REGION + bOff + koff);
            ldsm4(&bfh[4], ab + 2 * REGION + bOff + 16 * ROWB + koff);
            ldsm4(&bfl[0], ab + 3 * REGION + bOff + koff);
            ldsm4(&bfl[4], ab + 3 * REGION + bOff + 16 * ROWB + koff);
#pragma unroll
            for (int i = 0; i < 4; i++)
                ldsm4(&af[i * 4], ab + aOff + (unsigned)i * (16 * ROWB) + koff);
#pragma unroll
            for (int i = 0; i < 4; i++) {
#pragma unroll
                for (int j = 0; j < 4; j++) mma16816(&acc[(i * 4 + j) * 4], &af[i * 4], &bfh[j * 2]);
#pragma unroll
                for (int j = 0; j < 4; j++) mma16816(&acc[(i * 4 + j) * 4], &af[i * 4], &bfl[j * 2]);
            }
#pragma unroll
            for (int i = 0; i < 4; i++) {
                uint32_t al[4];
                ldsm4(al, ab + REGION + aOff + (unsigned)i * (16 * ROWB) + koff);
#pragma unroll
                for (int j = 0; j < 4; j++) mma16816(&acc[(i * 4 + j) * 4], al, &bfh[j * 2]);
            }
        }
        __syncthreads();
        if (c + 3 < 32) load_stage(sbase, s, c + 3, by, bx);
        cp_commit();
    }

    // epilogue: transpose through smem -> z^T [n][2048]
    __syncthreads();
    float* zsm = (float*)smem;           // [128 n][132 stride] floats = 67584B
    int q = lane >> 2, t4 = lane & 3;
#pragma unroll
    for (int i = 0; i < 4; i++)
#pragma unroll
        for (int j = 0; j < 4; j++) {
            int m = wm + i * 16 + q;
            int n = wn + j * 8 + t4 * 2;
            const float* p = &acc[(i * 4 + j) * 4];
            zsm[n * 132 + m]           = p[0];
            zsm[(n + 1) * 132 + m]     = p[1];
            zsm[n * 132 + m + 8]       = p[2];
            zsm[(n + 1) * 132 + m + 8] = p[3];
        }
    __syncthreads();
    int n0 = bx * 128, o0 = by * 128;
#pragma unroll
    for (int it = 0; it < 16; it++) {
        int task = it * 256 + tid;
        int row = task >> 5, col = task & 31;
        float4 v = *(const float4*)&zsm[row * 132 + col * 4];
        *(float4*)(g_zt + (size_t)(n0 + row) * 2048 + o0 + col * 4) = v;
    }
}

// ---------------- kernel 7: GLU gate + residual ----------------
__global__ void glu_kernel(const float* __restrict__ bias,
                           const float* __restrict__ hs,
                           float* __restrict__ out) {
    int n  = blockIdx.x;
    int h4 = threadIdx.x * 4;
    const float* zr = g_zt + (size_t)n * 2048;
    float4 za = *(const float4*)(zr + h4);
    float4 zg = *(const float4*)(zr + 1024 + h4);
    float4 ba = *(const float4*)(bias + h4);
    float4 bg = *(const float4*)(bias + 1024 + h4);
    float4 hv = *(const float4*)(hs + (size_t)n * 1024 + h4);
    float4 ov;
    ov.x = hv.x + (za.x + ba.x) * (1.0f / (1.0f + expf(-(zg.x + bg.x))));
    ov.y = hv.y + (za.y + ba.y) * (1.0f / (1.0f + expf(-(zg.y + bg.y))));
    ov.z = hv.z + (za.z + ba.z) * (1.0f / (1.0f + expf(-(zg.z + bg.z))));
    ov.w = hv.w + (za.w + ba.w) * (1.0f / (1.0f + expf(-(zg.w + bg.w))));
    *(float4*)(out + (size_t)n * 1024 + h4) = ov;
}

// ---------------- launch ----------------
extern "C" void kernel_launch(void* const* d_in, const int* in_sizes, int n_in,
                              void* d_out, int out_size) {
    const float* hidden     = (const float*)d_in[0];
    const float* attn_mask  = (const float*)d_in[1];
    const float* norm_w     = (const float*)d_in[2];
    const float* log_dt     = (const float*)d_in[3];
    const float* log_A_real = (const float*)d_in[4];
    const float* A_imag     = (const float*)d_in[5];
    const float* C_real     = (const float*)d_in[6];
    const float* C_imag     = (const float*)d_in[7];
    const float* Dvec       = (const float*)d_in[8];
    const float* out_w      = (const float*)d_in[9];
    const float* out_b      = (const float*)d_in[10];
    float* out = (float*)d_out;

    cudaFuncSetAttribute(gemm_mma_kernel, cudaFuncAttributeMaxDynamicSharedMemorySize, GEMM_SMEM);

    precompute_kernel<<<(Hh * Nn + 127) / 128, 128>>>(log_dt, log_A_real, A_imag, C_real, C_imag);
    rstd_kernel<<<(Bb * Ll * 32) / 256, 256>>>(hidden);
    norm_transpose_kernel<<<dim3(Hh / 32, Ll / 32, Bb), dim3(32, 8)>>>(hidden, attn_mask, norm_w);
    scan_local_kernel<<<(Bb * Hh * 32) / 256, 256>>>();
    scan_combine_kernel<<<(Bb * Hh * Nn) / 256, 256>>>();
    convert_w_kernel<<<(2048 * 512) / 256, 256>>>(out_w);
    scan_out_kernel<<<(Bb * Hh * 32) / 256, 256>>>(Dvec);
    transpose_yg_kernel<<<dim3(Hh / 64, Ll / 32, Bb), dim3(32, 8)>>>();
    gemm_mma_kernel<<<dim3(16, 128), 256, GEMM_SMEM>>>();
    glu_kernel<<<Bb * Ll, 256>>>(out_b, hidden, out);
}

// round 4
// speedup vs baseline: 3.3942x; 1.8089x over previous
#include <cuda_runtime.h>
#include <cuda_fp16.h>
#include <math.h>
#include <stdint.h>

// Problem constants
#define Bb 4
#define Ll 4096
#define Hh 1024
#define Nn 16
#define Pc 64           // chunk length
#define NCk 64          // Ll / Pc
#define EPSV 1e-6f

// ---------------- scratch (static device globals; no allocation) ----------------
__device__ float  g_u  [(size_t)Bb*Hh*Ll];   // normalized, masked, (B,H,L)  64MB
__device__ float  g_rstd[Bb*Ll];
__device__ float2 g_lam [Hh*Nn];
__device__ float2 g_lamP[Hh*Nn];
__device__ float2 g_cd2 [Hh*Nn];
__device__ float2 g_Sloc[(size_t)Bb*Hh*NCk*Nn];   // 33.5MB
__device__ float2 g_Sin [(size_t)Bb*Hh*NCk*Nn];   // 33.5MB
__device__ __half g_wf16[2048u*1024u];            // W fp16 [o][k]      4MB
__device__ __half g_yf16[(size_t)1024u*16384u];   // Y fp16 [k=h][n]   32MB

// ================= PTX helpers (legal on base compute_103) =================
__device__ __forceinline__ uint32_t smem_u32(const void* p) {
    uint32_t a;
    asm("{ .reg .u64 t; cvta.to.shared.u64 t, %1; cvt.u32.u64 %0, t; }" : "=r"(a) : "l"(p));
    return a;
}
__device__ __forceinline__ void cp16(uint32_t dst, const void* src) {
    asm volatile("cp.async.cg.shared.global [%0], [%1], 16;" :: "r"(dst), "l"(src));
}
__device__ __forceinline__ void cp_commit() { asm volatile("cp.async.commit_group;"); }
__device__ __forceinline__ void cp_wait2()  { asm volatile("cp.async.wait_group 2;"); }
__device__ __forceinline__ void ldsm4(uint32_t* r, uint32_t addr) {
    asm volatile("ldmatrix.sync.aligned.m8n8.x4.shared.b16 {%0,%1,%2,%3}, [%4];"
                 : "=r"(r[0]), "=r"(r[1]), "=r"(r[2]), "=r"(r[3]) : "r"(addr));
}
__device__ __forceinline__ void ldsm4t(uint32_t* r, uint32_t addr) {
    asm volatile("ldmatrix.sync.aligned.m8n8.x4.trans.shared.b16 {%0,%1,%2,%3}, [%4];"
                 : "=r"(r[0]), "=r"(r[1]), "=r"(r[2]), "=r"(r[3]) : "r"(addr));
}
__device__ __forceinline__ void mma16816(float* d, const uint32_t* a, const uint32_t* b) {
    asm volatile("mma.sync.aligned.m16n8k16.row.col.f32.f16.f16.f32 "
                 "{%0,%1,%2,%3}, {%4,%5,%6,%7}, {%8,%9}, {%0,%1,%2,%3};"
                 : "+f"(d[0]), "+f"(d[1]), "+f"(d[2]), "+f"(d[3])
                 : "r"(a[0]), "r"(a[1]), "r"(a[2]), "r"(a[3]), "r"(b[0]), "r"(b[1]));
}

// ---------------- kernel 0: per-(h,n) constants (double) + W fp32->fp16 ----------------
__global__ void fused_pre_kernel(const float* __restrict__ log_dt,
                                 const float* __restrict__ log_A_real,
                                 const float* __restrict__ A_imag,
                                 const float* __restrict__ C_real,
                                 const float* __restrict__ C_imag,
                                 const float* __restrict__ wmat) {
    unsigned int bid = blockIdx.x;
    if (bid < 8192u) {   // convert 2048x1024 weights
        unsigned int i = bid * 256 + threadIdx.x;
        g_wf16[i] = __float2half_rn(wmat[i]);
        return;
    }
    int idx = (int)(bid - 8192u) * 256 + threadIdx.x;
    if (idx >= Hh * Nn) return;
    int h = idx / Nn;
    double dt  = exp((double)log_dt[h]);
    double Are = -exp((double)log_A_real[idx]);
    double Aim = (double)A_imag[idx];
    double dre = Are * dt, dim = Aim * dt;
    double er  = exp(dre);
    double lr  = er * cos(dim), li = er * sin(dim);
    g_lam[idx] = make_float2((float)lr, (float)li);
    double erp = exp(dre * (double)Pc);
    g_lamP[idx] = make_float2((float)(erp * cos(dim * (double)Pc)),
                              (float)(erp * sin(dim * (double)Pc)));
    double e1r = lr - 1.0, e1i = li;
    double Cr = (double)C_real[idx], Ci = (double)C_imag[idx];
    double nr = Cr * e1r - Ci * e1i;
    double ni = Cr * e1i + Ci * e1r;
    double den = Are * Are + Aim * Aim;
    double cdr = (nr * Are + ni * Aim) / den;
    double cdi = (ni * Are - nr * Aim) / den;
    g_cd2[idx] = make_float2((float)(2.0 * cdr), (float)(2.0 * cdi));
}

// ---------------- kernel 1: RMSNorm rstd ----------------
__global__ void rstd_kernel(const float* __restrict__ hs) {
    int gt   = blockIdx.x * blockDim.x + threadIdx.x;
    int row  = gt >> 5;
    int lane = gt & 31;
    if (row >= Bb * Ll) return;
    const float4* rp = (const float4*)(hs + (size_t)row * Hh);
    float s = 0.f;
#pragma unroll
    for (int i = 0; i < 8; i++) {
        float4 v = rp[i * 32 + lane];
        s += v.x * v.x + v.y * v.y + v.z * v.z + v.w * v.w;
    }
#pragma unroll
    for (int o = 16; o; o >>= 1) s += __shfl_xor_sync(0xffffffffu, s, o);
    if (lane == 0) g_rstd[row] = rsqrtf(s * (1.0f / Hh) + EPSV);
}

// ---------------- kernel 2: normalize + mask + transpose to (B,H,L) ----------------
__global__ void norm_transpose_kernel(const float* __restrict__ hs,
                                      const float* __restrict__ mask,
                                      const float* __restrict__ w) {
    __shared__ float tile[32][33];
    int b  = blockIdx.z;
    int l0 = blockIdx.y * 32;
    int h0 = blockIdx.x * 32;
    int tx = threadIdx.x, ty = threadIdx.y;
    float wv = w[h0 + tx];
#pragma unroll
    for (int r = 0; r < 4; r++) {
        int l = l0 + ty + r * 8;
        float sc = g_rstd[b * Ll + l] * mask[b * Ll + l];
        tile[ty + r * 8][tx] = hs[((size_t)(b * Ll + l)) * Hh + h0 + tx] * sc * wv;
    }
    __syncthreads();
#pragma unroll
    for (int r = 0; r < 4; r++) {
        int h = h0 + ty + r * 8;
        g_u[((size_t)(b * Hh + h)) * Ll + l0 + tx] = tile[tx][ty + r * 8];
    }
}

// ---------------- kernel 3: per-chunk local end-states (Pc=64, 2 warps/(b,h)) -------
__global__ void scan_local_kernel() {
    int gt = blockIdx.x * blockDim.x + threadIdx.x;
    int w  = gt >> 5;
    int lane = gt & 31;
    int bh = w >> 1;
    int c  = ((w & 1) << 5) | lane;
    int hh = bh & (Hh - 1);
    float lr[Nn], li[Nn], sr[Nn], si[Nn];
#pragma unroll
    for (int n = 0; n < Nn; n++) {
        float2 v = g_lam[hh * Nn + n];
        lr[n] = v.x; li[n] = v.y; sr[n] = 0.f; si[n] = 0.f;
    }
    const float4* up = (const float4*)(g_u + (size_t)bh * Ll + c * Pc);
#pragma unroll 2
    for (int q = 0; q < Pc / 4; q++) {
        float4 uv = up[q];
        float xs[4] = {uv.x, uv.y, uv.z, uv.w};
#pragma unroll
        for (int e = 0; e < 4; e++) {
            float x = xs[e];
#pragma unroll
            for (int n = 0; n < Nn; n++) {
                float nr = fmaf(lr[n], sr[n], fmaf(-li[n], si[n], x));
                float ni = fmaf(lr[n], si[n], li[n] * sr[n]);
                sr[n] = nr; si[n] = ni;
            }
        }
    }
    float2* outp = g_Sloc + ((size_t)bh * NCk + c) * Nn;
#pragma unroll
    for (int n = 0; n < Nn; n++) outp[n] = make_float2(sr[n], si[n]);
}

// ---------------- kernel 4: inter-chunk combine ----------------
__global__ void scan_combine_kernel() {
    int t = blockIdx.x * blockDim.x + threadIdx.x;
    if (t >= Bb * Hh * Nn) return;
    int n  = t & (Nn - 1);
    int bh = t >> 4;
    int hh = bh & (Hh - 1);
    float2 lp = g_lamP[hh * Nn + n];
    float sre = 0.f, sim = 0.f;
#pragma unroll
    for (int c = 0; c < NCk; c++) {
        size_t idx = ((size_t)bh * NCk + c) * Nn + n;
        g_Sin[idx] = make_float2(sre, sim);
        float2 sl = g_Sloc[idx];
        float nr = fmaf(lp.x, sre, fmaf(-lp.y, sim, sl.x));
        float ni = fmaf(lp.x, sim, fmaf(lp.y, sre, sl.y));
        sre = nr; sim = ni;
    }
}

// ---------------- kernel 5: output scan + D skip + exact GELU -> fp16 [h][n] -------
__global__ void scan_out_kernel(const float* __restrict__ Dvec) {
    int gt = blockIdx.x * blockDim.x + threadIdx.x;
    int w  = gt >> 5;
    int lane = gt & 31;
    int bh = w >> 1;
    int c  = ((w & 1) << 5) | lane;
    int hh = bh & (Hh - 1);
    int b  = bh >> 10;
    float lr[Nn], li[Nn], cr[Nn], ci[Nn], sr[Nn], si[Nn];
#pragma unroll
    for (int n = 0; n < Nn; n++) {
        float2 v = g_lam[hh * Nn + n];  lr[n] = v.x; li[n] = v.y;
        float2 cc = g_cd2[hh * Nn + n]; cr[n] = cc.x; ci[n] = cc.y;
        float2 s0 = g_Sin[((size_t)bh * NCk + c) * Nn + n];
        sr[n] = s0.x; si[n] = s0.y;
    }
    float Dh = Dvec[hh];
    const float4* up = (const float4*)(g_u + (size_t)bh * Ll + c * Pc);
    uint2* yp = (uint2*)(g_yf16 + (size_t)hh * 16384 + (size_t)b * 4096 + c * Pc);
#pragma unroll 2
    for (int q = 0; q < Pc / 4; q++) {
        float4 uv = up[q];
        float xs[4] = {uv.x, uv.y, uv.z, uv.w};
        float ys[4];
#pragma unroll
        for (int e = 0; e < 4; e++) {
            float x = xs[e];
            float y = Dh * x;
#pragma unroll
            for (int n = 0; n < Nn; n++) {
                float nr = fmaf(lr[n], sr[n], fmaf(-li[n], si[n], x));
                float ni = fmaf(lr[n], si[n], li[n] * sr[n]);
                sr[n] = nr; si[n] = ni;
                y = fmaf(cr[n], nr, y);
                y = fmaf(-ci[n], ni, y);
            }
            ys[e] = 0.5f * y * (1.0f + erff(y * 0.70710678118654752f));
        }
        __half2 h2a = __floats2half2_rn(ys[0], ys[1]);
        __half2 h2b = __floats2half2_rn(ys[2], ys[3]);
        uint2 pk;
        pk.x = *(uint32_t*)&h2a;
        pk.y = *(uint32_t*)&h2b;
        yp[q] = pk;
    }
}

// ---------------- kernel 6: fp16 1-pass GEMM + GLU + residual ----------------
// A-tile: 128 rows = [64 a-rows (o0..o0+63) ; 64 gate-rows (1024+o0..)], k-chunk 32.
// B-tile: 128 n cols, loaded [k][n] and consumed via ldmatrix.trans.
#define KC 32
#define ROWA 80                         // 64B data + 16 pad
#define ROWBB 272                       // 256B data + 16 pad
#define A_REG (128*ROWA)                // 10240
#define B_REG (KC*ROWBB)                // 8704
#define STG (A_REG + B_REG)             // 18944
#define NSTG 4
#define GSMEM (NSTG*STG)                // 75776

__device__ __forceinline__ void load_stage(uint32_t sbase, int s, int chunk, int by, int bx) {
    int tid = threadIdx.x;
    uint32_t stb = sbase + s * STG;
    // A: 128 rows x 64B  (512 cp16)
#pragma unroll
    for (int i = 0; i < 2; i++) {
        int t = i * 256 + tid;
        int row = t >> 2, seg = t & 3;
        int wrow = (row < 64) ? (by * 64 + row) : (1024 + by * 64 + row - 64);
        cp16(stb + (unsigned)row * ROWA + seg * 16,
             g_wf16 + (size_t)wrow * 1024 + chunk * KC + seg * 8);
    }
    // B: 32 rows x 256B  (512 cp16)
#pragma unroll
    for (int i = 0; i < 2; i++) {
        int t = i * 256 + tid;
        int row = t >> 4, seg = t & 15;
        cp16(stb + A_REG + (unsigned)row * ROWBB + seg * 16,
             g_yf16 + (size_t)(chunk * KC + row) * 16384 + bx * 128 + seg * 8);
    }
}

__global__ __launch_bounds__(256, 2) void gemm_glu_kernel(const float* __restrict__ bias,
                                                          const float* __restrict__ hs,
                                                          float* __restrict__ out) {
    extern __shared__ char smem[];
    uint32_t sbase = smem_u32(smem);
    int tid  = threadIdx.x;
    int wid  = tid >> 5;
    int lane = tid & 31;
    int by = blockIdx.x;   // o-tile (64 outputs): fast -> CTAs sharing B co-resident
    int bx = blockIdx.y;   // n-tile (128 cols)

    int wm = (wid & 1) * 64;
    int wn = (wid >> 1) * 32;
    uint32_t aOff = (uint32_t)(wm + (lane & 15)) * ROWA + (uint32_t)(lane >> 4) * 16;
    uint32_t bOff = (uint32_t)(lane & 15) * ROWBB + (uint32_t)(lane >> 4) * 16
                  + (uint32_t)wn * 2;

    float acc[64];
#pragma unroll
    for (int i = 0; i < 64; i++) acc[i] = 0.f;

#pragma unroll
    for (int p = 0; p < 3; p++) { load_stage(sbase, p, p, by, bx); cp_commit(); }

    for (int c = 0; c < 32; c++) {
        int s = c & 3;
        cp_wait2();
        __syncthreads();
        if (c + 3 < 32) load_stage(sbase, (c + 3) & 3, c + 3, by, bx);
        cp_commit();
        uint32_t ab = sbase + s * STG;
        uint32_t bb = ab + A_REG;
#pragma unroll
        for (int ks = 0; ks < 2; ks++) {
            uint32_t bf[8], af[16];
            ldsm4t(&bf[0], bb + bOff + (unsigned)ks * (16 * ROWBB));
            ldsm4t(&bf[4], bb + bOff + (unsigned)ks * (16 * ROWBB) + 32);
#pragma unroll
            for (int i = 0; i < 4; i++)
                ldsm4(&af[i * 4], ab + aOff + (unsigned)i * (16 * ROWA) + ks * 32);
#pragma unroll
            for (int i = 0; i < 4; i++)
#pragma unroll
                for (int j = 0; j < 4; j++)
                    mma16816(&acc[(i * 4 + j) * 4], &af[i * 4], &bf[j * 2]);
        }
    }

    // epilogue: stage accs through smem [n][132 floats], then GLU + residual
    __syncthreads();
    float* zsm = (float*)smem;
    int qr = lane >> 2, t4 = lane & 3;
#pragma unroll
    for (int i = 0; i < 4; i++)
#pragma unroll
        for (int j = 0; j < 4; j++) {
            int m = wm + i * 16 + qr;
            int n = wn + j * 8 + t4 * 2;
            const float* p = &acc[(i * 4 + j) * 4];
            zsm[n * 132 + m]           = p[0];
            zsm[(n + 1) * 132 + m]     = p[1];
            zsm[n * 132 + m + 8]       = p[2];
            zsm[(n + 1) * 132 + m + 8] = p[3];
        }
    __syncthreads();
    int n0 = bx * 128, o0 = by * 64;
#pragma unroll
    for (int it = 0; it < 8; it++) {
        int task = it * 256 + tid;
        int nrow = task >> 4, mg = (task & 15) * 4;
        float4 za = *(const float4*)&zsm[nrow * 132 + mg];
        float4 zg = *(const float4*)&zsm[nrow * 132 + 64 + mg];
        float4 ba = *(const float4*)(bias + o0 + mg);
        float4 bg = *(const float4*)(bias + 1024 + o0 + mg);
        size_t addr = (size_t)(n0 + nrow) * 1024 + o0 + mg;
        float4 hv = *(const float4*)(hs + addr);
        float4 ov;
        ov.x = hv.x + (za.x + ba.x) * (1.0f / (1.0f + expf(-(zg.x + bg.x))));
        ov.y = hv.y + (za.y + ba.y) * (1.0f / (1.0f + expf(-(zg.y + bg.y))));
        ov.z = hv.z + (za.z + ba.z) * (1.0f / (1.0f + expf(-(zg.z + bg.z))));
        ov.w = hv.w + (za.w + ba.w) * (1.0f / (1.0f + expf(-(zg.w + bg.w))));
        *(float4*)(out + addr) = ov;
    }
}

// ---------------- launch ----------------
extern "C" void kernel_launch(void* const* d_in, const int* in_sizes, int n_in,
                              void* d_out, int out_size) {
    const float* hidden     = (const float*)d_in[0];
    const float* attn_mask  = (const float*)d_in[1];
    const float* norm_w     = (const float*)d_in[2];
    const float* log_dt     = (const float*)d_in[3];
    const float* log_A_real = (const float*)d_in[4];
    const float* A_imag     = (const float*)d_in[5];
    const float* C_real     = (const float*)d_in[6];
    const float* C_imag     = (const float*)d_in[7];
    const float* Dvec       = (const float*)d_in[8];
    const float* out_w      = (const float*)d_in[9];
    const float* out_b      = (const float*)d_in[10];
    float* out = (float*)d_out;

    cudaFuncSetAttribute(gemm_glu_kernel, cudaFuncAttributeMaxDynamicSharedMemorySize, GSMEM);

    fused_pre_kernel<<<8192 + 64, 256>>>(log_dt, log_A_real, A_imag, C_real, C_imag, out_w);
    rstd_kernel<<<(Bb * Ll * 32) / 256, 256>>>(hidden);
    norm_transpose_kernel<<<dim3(Hh / 32, Ll / 32, Bb), dim3(32, 8)>>>(hidden, attn_mask, norm_w);
    scan_local_kernel<<<(Bb * Hh * 2 * 32) / 256, 256>>>();
    scan_combine_kernel<<<(Bb * Hh * Nn) / 256, 256>>>();
    scan_out_kernel<<<(Bb * Hh * 2 * 32) / 256, 256>>>(Dvec);
    gemm_glu_kernel<<<dim3(16, 128), 256, GSMEM>>>(out_b, hidden, out);
}